// round 1
// baseline (speedup 1.0000x reference)
#include <cuda_runtime.h>

// NATSearch: 2D neighborhood attention (NATTEN-style), fp32.
// N=4 images, H=W=64, C=64, HEADS=2, dh=32, K=7.
// Pipeline: qkv GEMM -> neighborhood attention + softmax -> proj GEMM.

#define NIMG   4
#define HW     64
#define CCH    64
#define NHEADS 2
#define DHEAD  32
#define KWIN   7
#define NPIX   (NIMG * HW * HW)   // 16384
#define QKVD   192
#define NBDIM  14                 // neighborhood tile extent per 8x8 query tile
#define NNB    (NBDIM * NBDIM)    // 196
#define PITCH  36                 // smem row pitch (floats), mult of 4 for LDS.128
#define QSCALE 0.17677669529663687f  // 32^-0.5

__device__ float g_qkv[NPIX * QKVD];   // [pix][192]: q(64) k(64) v(64), within 64: head*32+d
__device__ float g_att[NPIX * CCH];    // attention output before proj

// ---------------------------------------------------------------------------
// Kernel 1: qkv = x @ w_qkv + b_qkv   (x[pix][c] = vid[n][c][x][y])
// block: 192 threads (one per output col), 8 pixels per block (same image row)
// ---------------------------------------------------------------------------
__global__ void __launch_bounds__(192) qkv_kernel(const float* __restrict__ vid,
                                                  const float* __restrict__ w_qkv,
                                                  const float* __restrict__ b_qkv) {
    __shared__ float xs[8][64];
    const int tid  = threadIdx.x;
    const int pix0 = blockIdx.x * 8;
    const int n  = pix0 >> 12;
    const int xr = (pix0 >> 6) & 63;
    const int y0 = pix0 & 63;          // multiple of 8 -> float4 aligned
    const float* vbase = vid + n * 262144 + xr * 64 + y0;

    if (tid < 128) {
        const int c = tid >> 1, q = tid & 1;
        const float4 v4 = *(const float4*)(vbase + c * 4096 + q * 4);
        xs[q * 4 + 0][c] = v4.x;
        xs[q * 4 + 1][c] = v4.y;
        xs[q * 4 + 2][c] = v4.z;
        xs[q * 4 + 3][c] = v4.w;
    }
    __syncthreads();

    const int j = tid;
    float acc[8];
    const float bj = b_qkv[j];
#pragma unroll
    for (int p = 0; p < 8; p++) acc[p] = bj;

#pragma unroll 8
    for (int c = 0; c < 64; c++) {
        const float w = w_qkv[c * QKVD + j];
#pragma unroll
        for (int p = 0; p < 8; p++) acc[p] += xs[p][c] * w;
    }

    const float sc = (j < 64) ? QSCALE : 1.0f;   // scale q by dh^-0.5
#pragma unroll
    for (int p = 0; p < 8; p++) g_qkv[(pix0 + p) * QKVD + j] = acc[p] * sc;
}

// ---------------------------------------------------------------------------
// Kernel 2: neighborhood attention. Block = (tile 8x8 queries, head, image),
// 64 threads = one query each. k/v 14x14 neighborhood staged in shared.
// ---------------------------------------------------------------------------
__global__ void __launch_bounds__(64) attn_kernel(const float* __restrict__ rpb) {
    extern __shared__ float sm[];
    float* ks = sm;                       // [196][PITCH]
    float* vs = sm + NNB * PITCH;         // [196][PITCH]
    float* rs = vs + NNB * PITCH;         // [169] rpb for this head

    const int tid  = threadIdx.x;
    const int head = blockIdx.y;
    const int n    = blockIdx.z;
    const int x0   = (blockIdx.x >> 3) * 8;
    const int y0   = (blockIdx.x & 7) * 8;
    const int rb   = min(max(x0 - 3, 0), 50);   // neighborhood row base
    const int cb   = min(max(y0 - 3, 0), 50);   // neighborhood col base

    // stage k/v tile: 196 nb pixels x 8 float4 each for k and v
    for (int i = tid; i < NNB * 8; i += 64) {
        const int nb = i >> 3, dq = i & 7;
        const int gr = rb + nb / NBDIM, gc = cb + nb % NBDIM;
        const float* src = g_qkv + (size_t)(n * 4096 + gr * 64 + gc) * QKVD + head * DHEAD + dq * 4;
        *(float4*)(ks + nb * PITCH + dq * 4) = *(const float4*)(src + 64);
        *(float4*)(vs + nb * PITCH + dq * 4) = *(const float4*)(src + 128);
    }
    for (int i = tid; i < 169; i += 64) rs[i] = rpb[head * 169 + i];
    __syncthreads();

    const int qx = tid >> 3, qy = tid & 7;
    const int xx = x0 + qx, yy = y0 + qy;

    float q[32];
    {
        const float* qp = g_qkv + (size_t)(n * 4096 + xx * 64 + yy) * QKVD + head * DHEAD;
#pragma unroll
        for (int dq = 0; dq < 8; dq++) {
            const float4 t = *(const float4*)(qp + dq * 4);
            q[dq * 4 + 0] = t.x; q[dq * 4 + 1] = t.y;
            q[dq * 4 + 2] = t.z; q[dq * 4 + 3] = t.w;
        }
    }

    const int sx = min(max(xx - 3, 0), 57), sy = min(max(yy - 3, 0), 57);
    const int r0 = sx - rb, c0 = sy - cb;          // base index into shared tile
    const int bh = sx - xx + 6, bw = sy - yy + 6;  // base index into rpb

    float lg[49];
#pragma unroll
    for (int a = 0; a < KWIN; a++) {
#pragma unroll
        for (int b = 0; b < KWIN; b++) {
            const float* kp = ks + ((r0 + a) * NBDIM + c0 + b) * PITCH;
            float acc0 = rs[(bh + a) * 13 + bw + b];
            float acc1 = 0.f;
#pragma unroll
            for (int dq = 0; dq < 8; dq++) {
                const float4 k4 = *(const float4*)(kp + dq * 4);
                acc0 += q[dq * 4 + 0] * k4.x + q[dq * 4 + 2] * k4.z;
                acc1 += q[dq * 4 + 1] * k4.y + q[dq * 4 + 3] * k4.w;
            }
            lg[a * KWIN + b] = acc0 + acc1;
        }
    }

    float m = lg[0];
#pragma unroll
    for (int i = 1; i < 49; i++) m = fmaxf(m, lg[i]);
    float s = 0.f;
#pragma unroll
    for (int i = 0; i < 49; i++) { const float e = __expf(lg[i] - m); lg[i] = e; s += e; }
    const float inv = 1.0f / s;

    float o[32];
#pragma unroll
    for (int d = 0; d < 32; d++) o[d] = 0.f;
#pragma unroll
    for (int a = 0; a < KWIN; a++) {
#pragma unroll
        for (int b = 0; b < KWIN; b++) {
            const float w = lg[a * KWIN + b];
            const float* vp = vs + ((r0 + a) * NBDIM + c0 + b) * PITCH;
#pragma unroll
            for (int dq = 0; dq < 8; dq++) {
                const float4 v4 = *(const float4*)(vp + dq * 4);
                o[dq * 4 + 0] += w * v4.x; o[dq * 4 + 1] += w * v4.y;
                o[dq * 4 + 2] += w * v4.z; o[dq * 4 + 3] += w * v4.w;
            }
        }
    }

    float* op = g_att + (size_t)(n * 4096 + xx * 64 + yy) * CCH + head * DHEAD;
#pragma unroll
    for (int dq = 0; dq < 8; dq++) {
        float4 t;
        t.x = o[dq * 4 + 0] * inv; t.y = o[dq * 4 + 1] * inv;
        t.z = o[dq * 4 + 2] * inv; t.w = o[dq * 4 + 3] * inv;
        *(float4*)(op + dq * 4) = t;
    }
}

// ---------------------------------------------------------------------------
// Kernel 3: out = g_att @ w_proj + b_proj, plus zero-fill of tail (inds).
// block: 128 threads = 64 cols x 2 pixel-groups, 16 pixels per block.
// ---------------------------------------------------------------------------
__global__ void __launch_bounds__(128) proj_kernel(const float* __restrict__ w_proj,
                                                   const float* __restrict__ b_proj,
                                                   float* __restrict__ out, int out_size) {
    __shared__ float xs[16][64];
    const int tid  = threadIdx.x;
    const int pix0 = blockIdx.x * 16;
    const float* src = g_att + (size_t)pix0 * 64;

#pragma unroll
    for (int i = tid; i < 256; i += 128) {
        const float4 t = *(const float4*)(src + i * 4);
        const int p = (i * 4) >> 6, c = (i * 4) & 63;
        xs[p][c] = t.x; xs[p][c + 1] = t.y; xs[p][c + 2] = t.z; xs[p][c + 3] = t.w;
    }
    __syncthreads();

    const int j = tid & 63, pg = tid >> 6;
    float acc[8];
    const float bj = b_proj[j];
#pragma unroll
    for (int p = 0; p < 8; p++) acc[p] = bj;

#pragma unroll 8
    for (int c = 0; c < 64; c++) {
        const float w = w_proj[c * 64 + j];
#pragma unroll
        for (int p = 0; p < 8; p++) acc[p] += xs[pg * 8 + p][c] * w;
    }
#pragma unroll
    for (int p = 0; p < 8; p++) out[(pix0 + pg * 8 + p) * 64 + j] = acc[p];

    // zero the inds tail (and any extra output elements)
    if (blockIdx.x == 0) {
        for (int i = NPIX * CCH + tid; i < out_size; i += 128) out[i] = 0.0f;
    }
}

// ---------------------------------------------------------------------------
extern "C" void kernel_launch(void* const* d_in, const int* in_sizes, int n_in,
                              void* d_out, int out_size) {
    const float* vid    = (const float*)d_in[0];
    const float* w_qkv  = (const float*)d_in[4];
    const float* b_qkv  = (const float*)d_in[5];
    const float* rpb    = (const float*)d_in[6];
    const float* w_proj = (const float*)d_in[7];
    const float* b_proj = (const float*)d_in[8];
    float* out = (float*)d_out;

    qkv_kernel<<<NPIX / 8, 192>>>(vid, w_qkv, b_qkv);

    const int smem = (2 * NNB * PITCH + 169) * (int)sizeof(float);  // ~57 KB
    cudaFuncSetAttribute(attn_kernel, cudaFuncAttributeMaxDynamicSharedMemorySize, smem);
    attn_kernel<<<dim3(64, NHEADS, NIMG), 64, smem>>>(rpb);

    proj_kernel<<<NPIX / 16, 128>>>(w_proj, b_proj, out, out_size);
}